// round 1
// baseline (speedup 1.0000x reference)
#include <cuda_runtime.h>
#include <math.h>

static constexpr int BATCH = 4;
static constexpr int MG = 4;           // aligned groups
static constexpr int C = 32;
static constexpr int S = 32 * 32 * 32; // spatial voxels
static constexpr float SCALE = 0.17677669529663687f; // 1/sqrt(32)

// ---------------- device scratch (no runtime allocation allowed) --------------
__device__ float g_u[4 * C * S];       // u_j[c,s] for j=0..3 (batch-independent)
__device__ float g_vt[C * S];          // Wv4 @ token
__device__ float g_l4[S];              // logit of token-vs-token (batch-independent)
__device__ float g_h[BATCH * 64 * S];  // conv1+gelu intermediate
__device__ float g_wt1[128 * 125 * 64];// conv1 weights transposed [cin][tap][co]
__device__ float g_wt2[64 * 125 * 32]; // conv2 weights transposed

// ---------------- weight transpose: [co][cin][tap] -> [cin][tap][co] ----------
__global__ void k_wt(const float* __restrict__ w, float* __restrict__ wt,
                     int cinN, int coN) {
    int n = cinN * 125 * coN;
    for (int i = blockIdx.x * blockDim.x + threadIdx.x; i < n;
         i += gridDim.x * blockDim.x) {
        int co  = i % coN;
        int tap = (i / coN) % 125;
        int cin = i / (coN * 125);
        wt[i] = w[(co * cinN + cin) * 125 + tap];
    }
}

// ---------------- K1: batch-independent attention precompute ------------------
__global__ void k_pre(const float* __restrict__ basis, const float* __restrict__ mixer,
                      const float* __restrict__ wq, const float* __restrict__ wk,
                      const float* __restrict__ wv) {
    __shared__ float smm[C * 8];
    __shared__ float smq[C * C];
    __shared__ float smk[5 * C * C];
    __shared__ float smv[C * C];
    int tid = threadIdx.x;
    for (int t = tid; t < C * 8; t += blockDim.x)     smm[t] = mixer[t];
    for (int t = tid; t < C * C; t += blockDim.x)     smq[t] = wq[4 * C * C + t];
    for (int t = tid; t < 5 * C * C; t += blockDim.x) smk[t] = wk[t];
    for (int t = tid; t < C * C; t += blockDim.x)     smv[t] = wv[4 * C * C + t];
    __syncthreads();

    int s = blockIdx.x * blockDim.x + tid;
    float br[8];
#pragma unroll
    for (int r = 0; r < 8; ++r) br[r] = basis[r * S + s];

    float tok[C];
#pragma unroll
    for (int c = 0; c < C; ++c) {
        float a = 0.f;
#pragma unroll
        for (int r = 0; r < 8; ++r) a += smm[c * 8 + r] * br[r];
        tok[c] = a;
    }
    float q4[C];
#pragma unroll
    for (int o = 0; o < C; ++o) {
        float a = 0.f;
        for (int c = 0; c < C; ++c) a += smq[o * C + c] * tok[c];
        q4[o] = a;
    }
    // u_j[c] = sum_o q4[o] * wk[j,o,c], j=0..3 stored; j=4 folded into logit4
    for (int j = 0; j < 4; ++j) {
        for (int c = 0; c < C; ++c) {
            float a = 0.f;
            for (int o = 0; o < C; ++o) a += q4[o] * smk[(j * C + o) * C + c];
            g_u[(j * C + c) * S + s] = a;
        }
    }
    float l4 = 0.f;
    for (int c = 0; c < C; ++c) {
        float a = 0.f;
        for (int o = 0; o < C; ++o) a += q4[o] * smk[(4 * C + o) * C + c];
        l4 += a * tok[c];
    }
    g_l4[s] = l4 * SCALE;

    for (int c = 0; c < C; ++c) {
        float a = 0.f;
        for (int cp = 0; cp < C; ++cp) a += smv[c * C + cp] * tok[cp];
        g_vt[c * S + s] = a;
    }
}

// ---------------- K2: per-(b,s) attention combine -> out = alpha * att --------
__global__ void k_attn(const float* __restrict__ x, const float* __restrict__ wv,
                       const float* __restrict__ alpha, float* __restrict__ out) {
    __shared__ float smwv[4 * C * C]; // [j][cp][c]
    int tid = threadIdx.x;
    for (int t = tid; t < 4 * C * C; t += blockDim.x) {
        int c  = t % C;
        int cp = (t / C) % C;
        int j  = t / (C * C);
        smwv[t] = wv[(j * C + c) * C + cp];
    }
    __syncthreads();

    int idx = blockIdx.x * blockDim.x + tid;
    int b = idx >> 15;
    int s = idx & (S - 1);
    const float* xb = x + (size_t)b * MG * C * S + s;

    float l[5];
    for (int j = 0; j < 4; ++j) {
        float a = 0.f;
        for (int c = 0; c < C; ++c)
            a += g_u[(j * C + c) * S + s] * xb[(j * C + c) * S];
        l[j] = a * SCALE;
    }
    l[4] = g_l4[s];

    float m = l[0];
#pragma unroll
    for (int j = 1; j < 5; ++j) m = fmaxf(m, l[j]);
    float p[5], sum = 0.f;
#pragma unroll
    for (int j = 0; j < 5; ++j) { p[j] = expf(l[j] - m); sum += p[j]; }
    float inv = 1.f / sum;
#pragma unroll
    for (int j = 0; j < 5; ++j) p[j] *= inv;

    float o_[C];
#pragma unroll
    for (int c = 0; c < C; ++c) o_[c] = p[4] * g_vt[c * S + s];
    for (int j = 0; j < 4; ++j) {
        for (int cp = 0; cp < C; ++cp) {
            float xv = p[j] * xb[(j * C + cp) * S];
            const float* wp = &smwv[(j * C + cp) * C];
#pragma unroll
            for (int c = 0; c < C; ++c) o_[c] += wp[c] * xv;
        }
    }
    float a0 = alpha[0];
#pragma unroll
    for (int c = 0; c < C; ++c)
        out[((size_t)b * C + c) * S + s] = a0 * o_[c];
}

// ---------------- 5x5x5 conv, pad 2. One block per (b,h,w), thread = cout ----
template <int CIN, int COUT, bool GELU, bool ACCUM>
__global__ void k_conv(const float* __restrict__ in, const float* __restrict__ wt,
                       const float* __restrict__ bias, float* __restrict__ out) {
    int w = blockIdx.x, h = blockIdx.y, b = blockIdx.z;
    int co = threadIdx.x;
    __shared__ float sx[5][36];
    float acc[32];
#pragma unroll
    for (int d = 0; d < 32; ++d) acc[d] = 0.f;

    for (int cin = 0; cin < CIN; ++cin) {
        const float* inch = in + (size_t)(b * CIN + cin) * S;
        for (int dh = 0; dh < 5; ++dh) {
            int ih = h + dh - 2;
            if ((unsigned)ih >= 32u) continue;   // uniform across block
            __syncthreads();
            for (int t = threadIdx.x; t < 180; t += COUT) {
                int ws = t / 36, dp = t - ws * 36;
                int iw = w + ws - 2, id = dp - 2;
                float v = 0.f;
                if ((unsigned)iw < 32u && (unsigned)id < 32u)
                    v = inch[ih * 1024 + iw * 32 + id];
                sx[ws][dp] = v;
            }
            __syncthreads();
            const float* wrow = wt + (cin * 125 + dh * 25) * COUT + co;
            for (int dw = 0; dw < 5; ++dw) {
                float xr[36];
#pragma unroll
                for (int t = 0; t < 36; ++t) xr[t] = sx[dw][t];
#pragma unroll
                for (int dd = 0; dd < 5; ++dd) {
                    float wval = wrow[(dw * 5 + dd) * COUT];
#pragma unroll
                    for (int d = 0; d < 32; ++d) acc[d] += xr[d + dd] * wval;
                }
            }
        }
    }
    float bs = bias[co];
    float* op = out + (((size_t)(b * COUT + co) * 32 + h) * 32 + w) * 32;
#pragma unroll
    for (int d = 0; d < 32; ++d) {
        float v = acc[d] + bs;
        if (GELU) v = 0.5f * v * (1.f + erff(v * 0.70710678118654752f));
        if (ACCUM) v += op[d];
        op[d] = v;
    }
}

// ------------------------------- launch ---------------------------------------
extern "C" void kernel_launch(void* const* d_in, const int* in_sizes, int n_in,
                              void* d_out, int out_size) {
    const float* x     = (const float*)d_in[0];
    const float* basis = (const float*)d_in[1];
    const float* mixer = (const float*)d_in[2];
    const float* wq    = (const float*)d_in[3];
    const float* wk    = (const float*)d_in[4];
    const float* wv    = (const float*)d_in[5];
    const float* c1w   = (const float*)d_in[6];
    const float* c1b   = (const float*)d_in[7];
    const float* c2w   = (const float*)d_in[8];
    const float* c2b   = (const float*)d_in[9];
    const float* alpha = (const float*)d_in[10];
    float* out = (float*)d_out;

    float *wt1, *wt2, *hbuf;
    cudaGetSymbolAddress((void**)&wt1, g_wt1);
    cudaGetSymbolAddress((void**)&wt2, g_wt2);
    cudaGetSymbolAddress((void**)&hbuf, g_h);

    k_wt<<<256, 256>>>(c1w, wt1, 128, 64);
    k_wt<<<64, 256>>>(c2w, wt2, 64, 32);
    k_pre<<<S / 256, 256>>>(basis, mixer, wq, wk, wv);
    k_attn<<<(BATCH * S) / 256, 256>>>(x, wv, alpha, out);
    k_conv<128, 64, true, false><<<dim3(32, 32, 4), 64>>>(x, wt1, c1b, hbuf);
    k_conv<64, 32, false, true><<<dim3(32, 32, 4), 32>>>(hbuf, wt2, c2b, out);
}